// round 8
// baseline (speedup 1.0000x reference)
#include <cuda_runtime.h>
#include <cstddef>

// Problem constants (fixed by setup_inputs)
#define B_   2
#define CV   64
#define CR   20
#define E_   64
#define CO   64
#define MV   100000
#define MR   50000
#define NV   262144      // v2p count per batch
#define NN   65536       // bundles per batch (N / bundle, bundle = 4)
#define TOTN (B_ * NN)   // 131072
#define CELLS (B_ * MR)  // 100000

typedef unsigned long long ull;

// ---------------- scratch (device globals: allocation-free) ----------------
__device__ float g_vT[(size_t)B_ * MV * CV];    // v_feat transposed: (B, Mv, 64)
__device__ float g_rT[(size_t)B_ * MR * CR];    // r_feat transposed: (B, Mr, 20)
__device__ float g_q [(size_t)TOTN * 64];       // q per bundle
__device__ float g_vbar[(size_t)CELLS * 64];    // per-cell summed vbar (RED target)
__device__ float g_WkqT[CR * 64];               // [c][f]
__device__ float g_WovT[64 * 64];               // [f][o]
__device__ int   g_iv[(size_t)B_ * NV];         // v indices (int32)
__device__ int   g_ir[(size_t)TOTN];            // r indices (int32)

// ---------------- setup: repack + zero vbar + weight folds ----------------
#define SETUP_REPACK_BLKS 512
#define SETUP_ZERO_BLKS   256
#define SETUP_GRID (SETUP_REPACK_BLKS + SETUP_ZERO_BLKS + 3)

__device__ __forceinline__ bool detect_int64(const int* __restrict__ p) {
    bool i64 = true;
#pragma unroll
    for (int i = 1; i < 32; i += 2) i64 &= (p[i] == 0);
    return i64;
}

__global__ __launch_bounds__(256) void setup_kernel(
    const void* __restrict__ v2p, const void* __restrict__ r2p,
    const float* __restrict__ Wq, const float* __restrict__ Wk,
    const float* __restrict__ Wv, const float* __restrict__ Wo) {
    __shared__ float sA[64 * 64];
    __shared__ float sB[64 * 64];

    int blk = blockIdx.x;
    int tid = threadIdx.x;

    if (blk < SETUP_REPACK_BLKS) {
        const int* pv = (const int*)v2p;
        const int* pr = (const int*)r2p;
        bool v64 = detect_int64(pv);
        bool r64 = detect_int64(pr);
        int t = blk * 256 + tid;
        int stride = SETUP_REPACK_BLKS * 256;
        for (int i = t; i < B_ * NV; i += stride)
            g_iv[i] = v64 ? pv[(size_t)4 * i] : pv[(size_t)2 * i];
        for (int i = t; i < TOTN; i += stride)
            g_ir[i] = r64 ? pr[(size_t)4 * i] : pr[(size_t)2 * i];
    } else if (blk < SETUP_REPACK_BLKS + SETUP_ZERO_BLKS) {
        // zero the RED accumulator
        float4* p = (float4*)g_vbar;
        int n4 = (CELLS * 64) / 4;
        int t = (blk - SETUP_REPACK_BLKS) * 256 + tid;
        int stride = SETUP_ZERO_BLKS * 256;
        float4 z = make_float4(0.f, 0.f, 0.f, 0.f);
        for (int i = t; i < n4; i += stride) p[i] = z;
    } else if (blk == SETUP_REPACK_BLKS + SETUP_ZERO_BLKS) {
        for (int i = tid; i < 64 * 64; i += 256) sA[i] = Wk[i];
        for (int i = tid; i < 64 * CR; i += 256) sB[i] = Wq[i];
        __syncthreads();
        for (int i = tid; i < CR * 64; i += 256) {
            int c = i >> 6, f = i & 63;
            float s = 0.f;
#pragma unroll
            for (int e = 0; e < 64; e++) s += sA[e * 64 + f] * sB[e * CR + c];
            g_WkqT[i] = s;  // [c][f]
        }
    } else {
        int half = blk - (SETUP_REPACK_BLKS + SETUP_ZERO_BLKS + 1);  // 0 or 1
        for (int i = tid; i < 64 * 64; i += 256) sA[i] = Wv[i];
        for (int i = tid; i < 64 * 64; i += 256) sB[i] = Wo[i];
        __syncthreads();
        for (int ii = half * 2048 + tid; ii < half * 2048 + 2048; ii += 256) {
            int f = ii >> 6, o = ii & 63;
            float s = 0.f;
#pragma unroll
            for (int e = 0; e < 64; e++) s += sB[o * 64 + e] * sA[e * 64 + f];
            g_WovT[ii] = s;  // [f][o]
        }
    }
}

// ---------------- generic tiled transpose: (B,R,C) -> (B,C,R) ----------------
__global__ void transpose_kernel(const float* __restrict__ in,
                                 float* __restrict__ out, int R, int C) {
    __shared__ float tile[32][33];
    int b = blockIdx.z;
    const float* inb = in + (size_t)b * R * C;
    float* outb = out + (size_t)b * R * C;

    int c = blockIdx.x * 32 + threadIdx.x;
#pragma unroll
    for (int i = threadIdx.y; i < 32; i += 8) {
        int r = blockIdx.y * 32 + i;
        if (r < R && c < C) tile[i][threadIdx.x] = inb[(size_t)r * C + c];
    }
    __syncthreads();
    int r2 = blockIdx.y * 32 + threadIdx.x;
#pragma unroll
    for (int i = threadIdx.y; i < 32; i += 8) {
        int cc = blockIdx.x * 32 + i;
        if (cc < C && r2 < R) outb[(size_t)cc * R + r2] = tile[threadIdx.x][i];
    }
}

// ---------------- q GEMM: g_q[n][f] = sum_c r_pp[n][c] * Wkq[c][f] ----------------
// 128 bundles/block; thread tile 8 f x 4 bundles (low regs -> high occupancy)
#define QTILE 128
#define QPAD 132
__global__ __launch_bounds__(256) void q_kernel() {
    __shared__ float sW[CR * 64];
    __shared__ float sRT[CR * QPAD];

    int tid = threadIdx.x;
    int tile = blockIdx.x * QTILE;

    for (int i = tid; i < CR * 64; i += 256) sW[i] = g_WkqT[i];
    if (tid < QTILE) {
        int n = tile + tid;
        int b = n >> 16;
        int ir = g_ir[n];
        const float4* src = (const float4*)(g_rT + ((size_t)b * MR + ir) * CR);
        float4 r0 = src[0], r1 = src[1], r2 = src[2], r3 = src[3], r4 = src[4];
        float rv[CR] = {r0.x, r0.y, r0.z, r0.w, r1.x, r1.y, r1.z, r1.w,
                        r2.x, r2.y, r2.z, r2.w, r3.x, r3.y, r3.z, r3.w,
                        r4.x, r4.y, r4.z, r4.w};
#pragma unroll
        for (int c = 0; c < CR; c++) sRT[c * QPAD + tid] = rv[c];
    }
    __syncthreads();

    int f0 = (tid & 7) * 8;
    int nl0 = (tid >> 3) * 4;

    ull acc2[4][4];   // p = f-pair, j = bundle
#pragma unroll
    for (int p = 0; p < 4; p++)
#pragma unroll
        for (int j = 0; j < 4; j++) acc2[p][j] = 0ull;

#pragma unroll
    for (int c = 0; c < CR; c++) {
        const float* wrow = sW + c * 64 + f0;
        ull w2[4];
#pragma unroll
        for (int p = 0; p < 4; p++) w2[p] = *(const ull*)(wrow + 2 * p);
        const float* vrow = sRT + c * QPAD + nl0;
        ull v2[4];
#pragma unroll
        for (int j = 0; j < 4; j++) {
            float vj = vrow[j];
            asm("mov.b64 %0, {%1, %1};" : "=l"(v2[j]) : "f"(vj));
        }
#pragma unroll
        for (int p = 0; p < 4; p++)
#pragma unroll
            for (int j = 0; j < 4; j++)
                asm("fma.rn.f32x2 %0, %1, %2, %0;"
                    : "+l"(acc2[p][j]) : "l"(w2[p]), "l"(v2[j]));
    }

#pragma unroll
    for (int j = 0; j < 4; j++) {
        int n = tile + nl0 + j;
        float a[8];
#pragma unroll
        for (int p = 0; p < 4; p++)
            asm("mov.b64 {%0, %1}, %2;" : "=f"(a[2 * p]), "=f"(a[2 * p + 1])
                : "l"(acc2[p][j]));
        float* dst = g_q + (size_t)n * 64 + f0;
        *(float4*)dst = make_float4(a[0], a[1], a[2], a[3]);
        *(float4*)(dst + 4) = make_float4(a[4], a[5], a[6], a[7]);
    }
}

// ---------------- attention kernel: gather v, softmax, RED into g_vbar ----------------
__global__ __launch_bounds__(256) void attn_kernel() {
    const unsigned FULL = 0xffffffffu;
    int gw = (blockIdx.x * 256 + threadIdx.x) >> 5;  // warp id, 4 bundles each
    int lane = threadIdx.x & 31;
    int sub = lane >> 3;
    int fl = lane & 7;

    int n = gw * 4 + sub;
    int b = n >> 16;

    // lanes 0..15: iv (16 values); lanes 16..19: ir (4 values)
    int ldv = 0;
    if (lane < 16) ldv = g_iv[(size_t)gw * 16 + lane];
    else if (lane < 20) ldv = g_ir[gw * 4 + (lane - 16)];

    const float4* qp = (const float4*)(g_q + (size_t)n * 64 + fl * 8);
    float4 q0 = qp[0];
    float4 q1 = qp[1];

    const float* vbase = g_vT + (size_t)b * MV * 64;
    float4 v0[4], v1[4];
    float s[4];
#pragma unroll
    for (int m = 0; m < 4; m++) {
        int ivm = __shfl_sync(FULL, ldv, sub * 4 + m);
        const float4* vp = (const float4*)(vbase + (size_t)ivm * 64 + fl * 8);
        v0[m] = vp[0];
        v1[m] = vp[1];
        float p = q0.x * v0[m].x + q0.y * v0[m].y + q0.z * v0[m].z + q0.w * v0[m].w
                + q1.x * v1[m].x + q1.y * v1[m].y + q1.z * v1[m].z + q1.w * v1[m].w;
        p += __shfl_xor_sync(FULL, p, 4);
        p += __shfl_xor_sync(FULL, p, 2);
        p += __shfl_xor_sync(FULL, p, 1);
        s[m] = p * 0.125f;  // 1/sqrt(E=64)
    }

    int ir_n = __shfl_sync(FULL, ldv, 16 + sub);

    float mx = fmaxf(fmaxf(s[0], s[1]), fmaxf(s[2], s[3]));
    float e0 = __expf(s[0] - mx), e1 = __expf(s[1] - mx);
    float e2 = __expf(s[2] - mx), e3 = __expf(s[3] - mx);
    float inv = 1.0f / (e0 + e1 + e2 + e3);
    e0 *= inv; e1 *= inv; e2 *= inv; e3 *= inv;

    float4 o0, o1;
    o0.x = e0 * v0[0].x + e1 * v0[1].x + e2 * v0[2].x + e3 * v0[3].x;
    o0.y = e0 * v0[0].y + e1 * v0[1].y + e2 * v0[2].y + e3 * v0[3].y;
    o0.z = e0 * v0[0].z + e1 * v0[1].z + e2 * v0[2].z + e3 * v0[3].z;
    o0.w = e0 * v0[0].w + e1 * v0[1].w + e2 * v0[2].w + e3 * v0[3].w;
    o1.x = e0 * v1[0].x + e1 * v1[1].x + e2 * v1[2].x + e3 * v1[3].x;
    o1.y = e0 * v1[0].y + e1 * v1[1].y + e2 * v1[2].y + e3 * v1[3].y;
    o1.z = e0 * v1[0].z + e1 * v1[1].z + e2 * v1[2].z + e3 * v1[3].z;
    o1.w = e0 * v1[0].w + e1 * v1[1].w + e2 * v1[2].w + e3 * v1[3].w;

    // reduce directly into per-cell accumulator (pre-GEMM scatter)
    float* dst = g_vbar + ((size_t)b * MR + ir_n) * 64 + fl * 8;
    asm volatile("red.global.add.v4.f32 [%0], {%1, %2, %3, %4};"
                 :: "l"(dst), "f"(o0.x), "f"(o0.y), "f"(o0.z), "f"(o0.w) : "memory");
    asm volatile("red.global.add.v4.f32 [%0], {%1, %2, %3, %4};"
                 :: "l"(dst + 4), "f"(o1.x), "f"(o1.y), "f"(o1.z), "f"(o1.w) : "memory");
}

// ---------------- dense output GEMM: out[b][o][m] = sum_f Wov[f][o] * vbar[m][f] ----------------
// 128 cells/block; thread tile 4 m x 8 o (low regs -> high occupancy)
#define OTILE 128
#define OPAD 132
#define OUT3_FLOATS (64 * 64 + 64 * OPAD)
#define OUT3_BYTES  (OUT3_FLOATS * 4)

__global__ __launch_bounds__(256) void out3_kernel(float* __restrict__ out) {
    extern __shared__ float dsm[];
    float* sW = dsm;                 // [f][o]
    float* sVT = dsm + 64 * 64;      // [f][cl]

    int tid = threadIdx.x;
    int b = blockIdx.y;
    int m0 = blockIdx.x * OTILE;

    {
        float4* d4 = (float4*)sW;
        const float4* s4 = (const float4*)g_WovT;
        for (int i = tid; i < 1024; i += 256) d4[i] = s4[i];
    }
    // coalesced load of 128 cells' vbar, transposed into sVT[f][cl]
    for (int i = tid; i < OTILE * 16; i += 256) {
        int cl = i >> 4;
        int c4 = i & 15;
        int m = m0 + cl;
        float4 v = make_float4(0.f, 0.f, 0.f, 0.f);
        if (m < MR)
            v = *(const float4*)(g_vbar + ((size_t)b * MR + m) * 64 + c4 * 4);
        int f = c4 * 4;
        sVT[(f + 0) * OPAD + cl] = v.x;
        sVT[(f + 1) * OPAD + cl] = v.y;
        sVT[(f + 2) * OPAD + cl] = v.z;
        sVT[(f + 3) * OPAD + cl] = v.w;
    }
    __syncthreads();

    int o0 = (tid & 7) * 8;
    int ml0 = (tid >> 3) * 4;

    ull acc2[2][8];   // p = m-pair, j = o
#pragma unroll
    for (int p = 0; p < 2; p++)
#pragma unroll
        for (int j = 0; j < 8; j++) acc2[p][j] = 0ull;

#pragma unroll 4
    for (int f = 0; f < 64; f++) {
        const float* wrow = sW + f * 64 + o0;
        float4 w0 = *(const float4*)wrow;
        float4 w1 = *(const float4*)(wrow + 4);
        float w[8] = {w0.x, w0.y, w0.z, w0.w, w1.x, w1.y, w1.z, w1.w};
        ull w2[8];
#pragma unroll
        for (int j = 0; j < 8; j++)
            asm("mov.b64 %0, {%1, %1};" : "=l"(w2[j]) : "f"(w[j]));
        const float* vrow = sVT + f * OPAD + ml0;
        ull v2[2];
#pragma unroll
        for (int p = 0; p < 2; p++) v2[p] = *(const ull*)(vrow + 2 * p);
#pragma unroll
        for (int p = 0; p < 2; p++)
#pragma unroll
            for (int j = 0; j < 8; j++)
                asm("fma.rn.f32x2 %0, %1, %2, %0;"
                    : "+l"(acc2[p][j]) : "l"(v2[p]), "l"(w2[j]));
    }

    if (m0 + ml0 < MR) {
#pragma unroll
        for (int j = 0; j < 8; j++) {
            int o = o0 + j;
            float a[4];
#pragma unroll
            for (int p = 0; p < 2; p++)
                asm("mov.b64 {%0, %1}, %2;" : "=f"(a[2 * p]), "=f"(a[2 * p + 1])
                    : "l"(acc2[p][j]));
            float* dst = out + ((size_t)b * CO + o) * MR + m0 + ml0;
            *(float4*)dst = make_float4(a[0], a[1], a[2], a[3]);
        }
    }
}

// ---------------- launch ----------------
extern "C" void kernel_launch(void* const* d_in, const int* in_sizes, int n_in,
                              void* d_out, int out_size) {
    const float* v_feat = (const float*)d_in[0];
    const float* r_feat = (const float*)d_in[1];
    const float* Wq = (const float*)d_in[2];
    const float* Wk = (const float*)d_in[3];
    const float* Wv = (const float*)d_in[4];
    const float* Wo = (const float*)d_in[5];
    const void* v2p = d_in[6];
    const void* r2p = d_in[7];
    float* out = (float*)d_out;

    float *vT, *rT;
    cudaGetSymbolAddress((void**)&vT, g_vT);
    cudaGetSymbolAddress((void**)&rT, g_rT);

    cudaFuncSetAttribute(out3_kernel, cudaFuncAttributeMaxDynamicSharedMemorySize,
                         OUT3_BYTES);

    // 1) setup: repack indices + zero vbar accumulator + fold weights
    setup_kernel<<<SETUP_GRID, 256>>>(v2p, r2p, Wq, Wk, Wv, Wo);

    // 2) layout transposes
    transpose_kernel<<<dim3((MV + 31) / 32, (CV + 31) / 32, B_), dim3(32, 8)>>>(v_feat, vT, CV, MV);
    transpose_kernel<<<dim3((MR + 31) / 32, (CR + 31) / 32, B_), dim3(32, 8)>>>(r_feat, rT, CR, MR);

    // 3) q GEMM (8f x 4n tile, high occupancy)
    q_kernel<<<TOTN / QTILE, 256>>>();

    // 4) attention + pre-GEMM scatter (RED into g_vbar)
    attn_kernel<<<TOTN / 32, 256>>>();

    // 5) dense Wov GEMM + direct store into final layout (4m x 8o tile)
    out3_kernel<<<dim3((MR + OTILE - 1) / OTILE, B_), 256, OUT3_BYTES>>>(out);
}

// round 9
// speedup vs baseline: 1.0666x; 1.0666x over previous
#include <cuda_runtime.h>
#include <cstddef>

// Problem constants (fixed by setup_inputs)
#define B_   2
#define CV   64
#define CR   20
#define E_   64
#define CO   64
#define MV   100000
#define MR   50000
#define NV   262144      // v2p count per batch
#define NN   65536       // bundles per batch (N / bundle, bundle = 4)
#define TOTN (B_ * NN)   // 131072
#define CELLS (B_ * MR)  // 100000

typedef unsigned long long ull;

// ---------------- scratch (device globals: allocation-free) ----------------
__device__ float g_vT[(size_t)B_ * MV * CV];    // v_feat transposed: (B, Mv, 64)
__device__ float g_qd[(size_t)CELLS * 64];      // dense q per cell: (B, Mr, 64)
__device__ float g_vbar[(size_t)CELLS * 64];    // per-cell summed vbar (RED target)
__device__ float g_WkqT[CR * 64];               // [c][f]
__device__ float g_WovT[64 * 64];               // [f][o]
__device__ int   g_iv[(size_t)B_ * NV];         // v indices (int32)
__device__ int   g_ir[(size_t)TOTN];            // r indices (int32)

// ---------------- setup: repack + zero vbar + weight folds ----------------
#define SETUP_REPACK_BLKS 512
#define SETUP_ZERO_BLKS   256
#define SETUP_GRID (SETUP_REPACK_BLKS + SETUP_ZERO_BLKS + 3)

__device__ __forceinline__ bool detect_int64(const int* __restrict__ p) {
    bool i64 = true;
#pragma unroll
    for (int i = 1; i < 32; i += 2) i64 &= (p[i] == 0);
    return i64;
}

__global__ __launch_bounds__(256) void setup_kernel(
    const void* __restrict__ v2p, const void* __restrict__ r2p,
    const float* __restrict__ Wq, const float* __restrict__ Wk,
    const float* __restrict__ Wv, const float* __restrict__ Wo) {
    __shared__ float sA[64 * 64];
    __shared__ float sB[64 * 64];

    int blk = blockIdx.x;
    int tid = threadIdx.x;

    if (blk < SETUP_REPACK_BLKS) {
        const int* pv = (const int*)v2p;
        const int* pr = (const int*)r2p;
        bool v64 = detect_int64(pv);
        bool r64 = detect_int64(pr);
        int t = blk * 256 + tid;
        int stride = SETUP_REPACK_BLKS * 256;
        for (int i = t; i < B_ * NV; i += stride)
            g_iv[i] = v64 ? pv[(size_t)4 * i] : pv[(size_t)2 * i];
        for (int i = t; i < TOTN; i += stride)
            g_ir[i] = r64 ? pr[(size_t)4 * i] : pr[(size_t)2 * i];
    } else if (blk < SETUP_REPACK_BLKS + SETUP_ZERO_BLKS) {
        // zero the RED accumulator
        float4* p = (float4*)g_vbar;
        int n4 = (CELLS * 64) / 4;
        int t = (blk - SETUP_REPACK_BLKS) * 256 + tid;
        int stride = SETUP_ZERO_BLKS * 256;
        float4 z = make_float4(0.f, 0.f, 0.f, 0.f);
        for (int i = t; i < n4; i += stride) p[i] = z;
    } else if (blk == SETUP_REPACK_BLKS + SETUP_ZERO_BLKS) {
        for (int i = tid; i < 64 * 64; i += 256) sA[i] = Wk[i];
        for (int i = tid; i < 64 * CR; i += 256) sB[i] = Wq[i];
        __syncthreads();
        for (int i = tid; i < CR * 64; i += 256) {
            int c = i >> 6, f = i & 63;
            float s = 0.f;
#pragma unroll
            for (int e = 0; e < 64; e++) s += sA[e * 64 + f] * sB[e * CR + c];
            g_WkqT[i] = s;  // [c][f]
        }
    } else {
        int half = blk - (SETUP_REPACK_BLKS + SETUP_ZERO_BLKS + 1);  // 0 or 1
        for (int i = tid; i < 64 * 64; i += 256) sA[i] = Wv[i];
        for (int i = tid; i < 64 * 64; i += 256) sB[i] = Wo[i];
        __syncthreads();
        for (int ii = half * 2048 + tid; ii < half * 2048 + 2048; ii += 256) {
            int f = ii >> 6, o = ii & 63;
            float s = 0.f;
#pragma unroll
            for (int e = 0; e < 64; e++) s += sB[o * 64 + e] * sA[e * 64 + f];
            g_WovT[ii] = s;  // [f][o]
        }
    }
}

// ---------------- generic tiled transpose: (B,R,C) -> (B,C,R) ----------------
__global__ void transpose_kernel(const float* __restrict__ in,
                                 float* __restrict__ out, int R, int C) {
    __shared__ float tile[32][33];
    int b = blockIdx.z;
    const float* inb = in + (size_t)b * R * C;
    float* outb = out + (size_t)b * R * C;

    int c = blockIdx.x * 32 + threadIdx.x;
#pragma unroll
    for (int i = threadIdx.y; i < 32; i += 8) {
        int r = blockIdx.y * 32 + i;
        if (r < R && c < C) tile[i][threadIdx.x] = inb[(size_t)r * C + c];
    }
    __syncthreads();
    int r2 = blockIdx.y * 32 + threadIdx.x;
#pragma unroll
    for (int i = threadIdx.y; i < 32; i += 8) {
        int cc = blockIdx.x * 32 + i;
        if (cc < C && r2 < R) outb[(size_t)cc * R + r2] = tile[threadIdx.x][i];
    }
}

// ---------------- dense q GEMM: g_qd[b][m][f] = sum_c r_feat[b][c][m] * Wkq[c][f] ----------------
// reads r_feat in native layout (coalesced along m) — no transpose, no gather
#define QD_TILE 128
#define QD_PAD 132
__global__ __launch_bounds__(256) void qd_kernel(const float* __restrict__ r_feat) {
    __shared__ float sW[CR * 64];       // [c][f]
    __shared__ float sR[CR * QD_PAD];   // [c][m-local]

    int tid = threadIdx.x;
    int b = blockIdx.y;
    int m0 = blockIdx.x * QD_TILE;

    for (int i = tid; i < CR * 64; i += 256) sW[i] = g_WkqT[i];
    for (int i = tid; i < CR * QD_TILE; i += 256) {
        int c = i / QD_TILE;
        int m = i - c * QD_TILE;
        float v = 0.f;
        if (m0 + m < MR) v = r_feat[((size_t)b * CR + c) * MR + m0 + m];
        sR[c * QD_PAD + m] = v;
    }
    __syncthreads();

    int f0 = (tid & 7) * 8;
    int ml0 = (tid >> 3) * 4;

    ull acc2[4][4];   // p = f-pair, j = m
#pragma unroll
    for (int p = 0; p < 4; p++)
#pragma unroll
        for (int j = 0; j < 4; j++) acc2[p][j] = 0ull;

#pragma unroll
    for (int c = 0; c < CR; c++) {
        const float* wrow = sW + c * 64 + f0;
        ull w2[4];
#pragma unroll
        for (int p = 0; p < 4; p++) w2[p] = *(const ull*)(wrow + 2 * p);
        const float* vrow = sR + c * QD_PAD + ml0;
        ull v2[4];
#pragma unroll
        for (int j = 0; j < 4; j++) {
            float vj = vrow[j];
            asm("mov.b64 %0, {%1, %1};" : "=l"(v2[j]) : "f"(vj));
        }
#pragma unroll
        for (int p = 0; p < 4; p++)
#pragma unroll
            for (int j = 0; j < 4; j++)
                asm("fma.rn.f32x2 %0, %1, %2, %0;"
                    : "+l"(acc2[p][j]) : "l"(w2[p]), "l"(v2[j]));
    }

#pragma unroll
    for (int j = 0; j < 4; j++) {
        int m = m0 + ml0 + j;
        if (m < MR) {
            float a[8];
#pragma unroll
            for (int p = 0; p < 4; p++)
                asm("mov.b64 {%0, %1}, %2;" : "=f"(a[2 * p]), "=f"(a[2 * p + 1])
                    : "l"(acc2[p][j]));
            float* dst = g_qd + ((size_t)b * MR + m) * 64 + f0;
            *(float4*)dst = make_float4(a[0], a[1], a[2], a[3]);
            *(float4*)(dst + 4) = make_float4(a[4], a[5], a[6], a[7]);
        }
    }
}

// ---------------- attention kernel: gather q + v, softmax, RED into g_vbar ----------------
__global__ __launch_bounds__(256) void attn_kernel() {
    const unsigned FULL = 0xffffffffu;
    int gw = (blockIdx.x * 256 + threadIdx.x) >> 5;  // warp id, 4 bundles each
    int lane = threadIdx.x & 31;
    int sub = lane >> 3;
    int fl = lane & 7;

    int n = gw * 4 + sub;
    int b = n >> 16;

    // lanes 0..15: iv (16 values); lanes 16..19: ir (4 values)
    int ldv = 0;
    if (lane < 16) ldv = g_iv[(size_t)gw * 16 + lane];
    else if (lane < 20) ldv = g_ir[gw * 4 + (lane - 16)];

    int ir_n = __shfl_sync(FULL, ldv, 16 + sub);

    // gather q row for this bundle's cell
    const float4* qp = (const float4*)(g_qd + ((size_t)b * MR + ir_n) * 64 + fl * 8);
    float4 q0 = qp[0];
    float4 q1 = qp[1];

    const float* vbase = g_vT + (size_t)b * MV * 64;
    float4 v0[4], v1[4];
    float s[4];
#pragma unroll
    for (int m = 0; m < 4; m++) {
        int ivm = __shfl_sync(FULL, ldv, sub * 4 + m);
        const float4* vp = (const float4*)(vbase + (size_t)ivm * 64 + fl * 8);
        v0[m] = vp[0];
        v1[m] = vp[1];
        float p = q0.x * v0[m].x + q0.y * v0[m].y + q0.z * v0[m].z + q0.w * v0[m].w
                + q1.x * v1[m].x + q1.y * v1[m].y + q1.z * v1[m].z + q1.w * v1[m].w;
        p += __shfl_xor_sync(FULL, p, 4);
        p += __shfl_xor_sync(FULL, p, 2);
        p += __shfl_xor_sync(FULL, p, 1);
        s[m] = p * 0.125f;  // 1/sqrt(E=64)
    }

    float mx = fmaxf(fmaxf(s[0], s[1]), fmaxf(s[2], s[3]));
    float e0 = __expf(s[0] - mx), e1 = __expf(s[1] - mx);
    float e2 = __expf(s[2] - mx), e3 = __expf(s[3] - mx);
    float inv = 1.0f / (e0 + e1 + e2 + e3);
    e0 *= inv; e1 *= inv; e2 *= inv; e3 *= inv;

    float4 o0, o1;
    o0.x = e0 * v0[0].x + e1 * v0[1].x + e2 * v0[2].x + e3 * v0[3].x;
    o0.y = e0 * v0[0].y + e1 * v0[1].y + e2 * v0[2].y + e3 * v0[3].y;
    o0.z = e0 * v0[0].z + e1 * v0[1].z + e2 * v0[2].z + e3 * v0[3].z;
    o0.w = e0 * v0[0].w + e1 * v0[1].w + e2 * v0[2].w + e3 * v0[3].w;
    o1.x = e0 * v1[0].x + e1 * v1[1].x + e2 * v1[2].x + e3 * v1[3].x;
    o1.y = e0 * v1[0].y + e1 * v1[1].y + e2 * v1[2].y + e3 * v1[3].y;
    o1.z = e0 * v1[0].z + e1 * v1[1].z + e2 * v1[2].z + e3 * v1[3].z;
    o1.w = e0 * v1[0].w + e1 * v1[1].w + e2 * v1[2].w + e3 * v1[3].w;

    // reduce directly into per-cell accumulator (pre-GEMM scatter)
    float* dst = g_vbar + ((size_t)b * MR + ir_n) * 64 + fl * 8;
    asm volatile("red.global.add.v4.f32 [%0], {%1, %2, %3, %4};"
                 :: "l"(dst), "f"(o0.x), "f"(o0.y), "f"(o0.z), "f"(o0.w) : "memory");
    asm volatile("red.global.add.v4.f32 [%0], {%1, %2, %3, %4};"
                 :: "l"(dst + 4), "f"(o1.x), "f"(o1.y), "f"(o1.z), "f"(o1.w) : "memory");
}

// ---------------- dense output GEMM: out[b][o][m] = sum_f Wov[f][o] * vbar[m][f] ----------------
// R7-measured shape: 256 cells/block, thread tile 8 m x 8 o
#define OPAD 260
#define OUT3_FLOATS (64 * 64 + 64 * OPAD)
#define OUT3_BYTES  (OUT3_FLOATS * 4)

__global__ __launch_bounds__(256) void out3_kernel(float* __restrict__ out) {
    extern __shared__ float dsm[];
    float* sW = dsm;                 // [f][o]
    float* sVT = dsm + 64 * 64;      // [f][cl]

    int tid = threadIdx.x;
    int b = blockIdx.y;
    int m0 = blockIdx.x * 256;

    {
        float4* d4 = (float4*)sW;
        const float4* s4 = (const float4*)g_WovT;
        for (int i = tid; i < 1024; i += 256) d4[i] = s4[i];
    }
    // coalesced load of 256 cells' vbar, transposed into sVT[f][cl]
    for (int i = tid; i < 256 * 16; i += 256) {
        int cl = i >> 4;
        int c4 = i & 15;
        int m = m0 + cl;
        float4 v = make_float4(0.f, 0.f, 0.f, 0.f);
        if (m < MR)
            v = *(const float4*)(g_vbar + ((size_t)b * MR + m) * 64 + c4 * 4);
        int f = c4 * 4;
        sVT[(f + 0) * OPAD + cl] = v.x;
        sVT[(f + 1) * OPAD + cl] = v.y;
        sVT[(f + 2) * OPAD + cl] = v.z;
        sVT[(f + 3) * OPAD + cl] = v.w;
    }
    __syncthreads();

    int o0 = (tid & 7) * 8;
    int ml0 = (tid >> 3) * 8;

    ull acc2[4][8];   // p = m-pair, j = o
#pragma unroll
    for (int p = 0; p < 4; p++)
#pragma unroll
        for (int j = 0; j < 8; j++) acc2[p][j] = 0ull;

#pragma unroll 4
    for (int f = 0; f < 64; f++) {
        const float* wrow = sW + f * 64 + o0;
        float4 w0 = *(const float4*)wrow;
        float4 w1 = *(const float4*)(wrow + 4);
        float w[8] = {w0.x, w0.y, w0.z, w0.w, w1.x, w1.y, w1.z, w1.w};
        ull w2[8];
#pragma unroll
        for (int j = 0; j < 8; j++)
            asm("mov.b64 %0, {%1, %1};" : "=l"(w2[j]) : "f"(w[j]));
        const float* vrow = sVT + f * OPAD + ml0;
        ull v2[4];
#pragma unroll
        for (int p = 0; p < 4; p++) v2[p] = *(const ull*)(vrow + 2 * p);
#pragma unroll
        for (int p = 0; p < 4; p++)
#pragma unroll
            for (int j = 0; j < 8; j++)
                asm("fma.rn.f32x2 %0, %1, %2, %0;"
                    : "+l"(acc2[p][j]) : "l"(v2[p]), "l"(w2[j]));
    }

    if (m0 + ml0 < MR) {
#pragma unroll
        for (int j = 0; j < 8; j++) {
            int o = o0 + j;
            float a[8];
#pragma unroll
            for (int p = 0; p < 4; p++)
                asm("mov.b64 {%0, %1}, %2;" : "=f"(a[2 * p]), "=f"(a[2 * p + 1])
                    : "l"(acc2[p][j]));
            float* dst = out + ((size_t)b * CO + o) * MR + m0 + ml0;
            *(float4*)dst = make_float4(a[0], a[1], a[2], a[3]);
            *(float4*)(dst + 4) = make_float4(a[4], a[5], a[6], a[7]);
        }
    }
}

// ---------------- launch ----------------
extern "C" void kernel_launch(void* const* d_in, const int* in_sizes, int n_in,
                              void* d_out, int out_size) {
    const float* v_feat = (const float*)d_in[0];
    const float* r_feat = (const float*)d_in[1];
    const float* Wq = (const float*)d_in[2];
    const float* Wk = (const float*)d_in[3];
    const float* Wv = (const float*)d_in[4];
    const float* Wo = (const float*)d_in[5];
    const void* v2p = d_in[6];
    const void* r2p = d_in[7];
    float* out = (float*)d_out;

    float* vT;
    cudaGetSymbolAddress((void**)&vT, g_vT);

    cudaFuncSetAttribute(out3_kernel, cudaFuncAttributeMaxDynamicSharedMemorySize,
                         OUT3_BYTES);

    // 1) setup: repack indices + zero vbar accumulator + fold weights
    setup_kernel<<<SETUP_GRID, 256>>>(v2p, r2p, Wq, Wk, Wv, Wo);

    // 2) v layout transpose (feature-contiguous gathers)
    transpose_kernel<<<dim3((MV + 31) / 32, (CV + 31) / 32, B_), dim3(32, 8)>>>(v_feat, vT, CV, MV);

    // 3) dense q GEMM straight from r_feat (no transpose, no gather)
    qd_kernel<<<dim3((MR + QD_TILE - 1) / QD_TILE, B_), 256>>>(r_feat);

    // 4) attention: gather q (by cell) + v (by index), softmax, RED into g_vbar
    attn_kernel<<<TOTN / 32, 256>>>();

    // 5) dense Wov GEMM + direct store into final layout
    out3_kernel<<<dim3((MR + 255) / 256, B_), 256, OUT3_BYTES>>>(out);
}

// round 10
// speedup vs baseline: 1.1260x; 1.0557x over previous
#include <cuda_runtime.h>
#include <cstddef>

// Problem constants (fixed by setup_inputs)
#define B_   2
#define CV   64
#define CR   20
#define E_   64
#define CO   64
#define MV   100000
#define MR   50000
#define NV   262144      // v2p count per batch
#define NN   65536       // bundles per batch (N / bundle, bundle = 4)
#define TOTN (B_ * NN)   // 131072
#define CELLS (B_ * MR)  // 100000

typedef unsigned long long ull;

// ---------------- scratch (device globals: allocation-free) ----------------
__device__ float g_vT[(size_t)B_ * MV * CV];    // v_feat transposed: (B, Mv, 64)
__device__ float g_qd[(size_t)CELLS * 64];      // dense q per cell: (B, Mr, 64)
__device__ float g_vbar[(size_t)CELLS * 64];    // per-cell summed vbar (RED target)
__device__ float g_WkqT[CR * 64];               // [c][f]
__device__ float g_WovT[64 * 64];               // [f][o]
__device__ int   g_iv[(size_t)B_ * NV];         // v indices (int32)
__device__ int   g_ir[(size_t)TOTN];            // r indices (int32)

__device__ __forceinline__ bool detect_int64(const int* __restrict__ p) {
    bool i64 = true;
#pragma unroll
    for (int i = 1; i < 32; i += 2) i64 &= (p[i] == 0);
    return i64;
}

// ---------------- phase1: vT transpose + repack + zero vbar + weight folds ----------------
// block ranges: [0, TR): v transpose; [TR, TR+RP): repack; [.., +ZR): zero; last 3: folds
#define TR_BX 3125                       // ceil(MV/32)
#define TR_BLKS (TR_BX * 2 * B_)         // 12500
#define RP_BLKS 256
#define ZR_BLKS 128
#define P1_GRID (TR_BLKS + RP_BLKS + ZR_BLKS + 3)

__global__ __launch_bounds__(256) void phase1_kernel(
    const float* __restrict__ v_feat,
    const void* __restrict__ v2p, const void* __restrict__ r2p,
    const float* __restrict__ Wq, const float* __restrict__ Wk,
    const float* __restrict__ Wv, const float* __restrict__ Wo) {
    __shared__ float sbuf[64 * 64 * 2];   // union: transpose tile / fold operands

    int blk = blockIdx.x;
    int tid = threadIdx.x;

    if (blk < TR_BLKS) {
        // ---- v transpose: (B, 64, Mv) -> (B, Mv, 64), 32x32 tiles ----
        float (*tile)[33] = (float (*)[33])sbuf;
        int bx = blk % TR_BX;
        int rest = blk / TR_BX;
        int by = rest & 1;          // 2 tiles over CV=64
        int b = rest >> 1;
        const float* inb = v_feat + (size_t)b * CV * MV;
        float* outb = g_vT + (size_t)b * MV * CV;

        int tx = tid & 31, ty = tid >> 5;
        int c = bx * 32 + tx;
#pragma unroll
        for (int i = ty; i < 32; i += 8) {
            int r = by * 32 + i;
            if (c < MV) tile[i][tx] = inb[(size_t)r * MV + c];
        }
        __syncthreads();
        int r2 = by * 32 + tx;
#pragma unroll
        for (int i = ty; i < 32; i += 8) {
            int cc = bx * 32 + i;
            if (cc < MV) outb[(size_t)cc * CV + r2] = tile[tx][i];
        }
    } else if (blk < TR_BLKS + RP_BLKS) {
        // ---- index repack (int32 or int64 source) ----
        const int* pv = (const int*)v2p;
        const int* pr = (const int*)r2p;
        bool v64 = detect_int64(pv);
        bool r64 = detect_int64(pr);
        int t = (blk - TR_BLKS) * 256 + tid;
        int stride = RP_BLKS * 256;
        for (int i = t; i < B_ * NV; i += stride)
            g_iv[i] = v64 ? pv[(size_t)4 * i] : pv[(size_t)2 * i];
        for (int i = t; i < TOTN; i += stride)
            g_ir[i] = r64 ? pr[(size_t)4 * i] : pr[(size_t)2 * i];
    } else if (blk < TR_BLKS + RP_BLKS + ZR_BLKS) {
        // ---- zero RED accumulator ----
        float4* p = (float4*)g_vbar;
        int n4 = (CELLS * 64) / 4;
        int t = (blk - TR_BLKS - RP_BLKS) * 256 + tid;
        int stride = ZR_BLKS * 256;
        float4 z = make_float4(0.f, 0.f, 0.f, 0.f);
        for (int i = t; i < n4; i += stride) p[i] = z;
    } else if (blk == TR_BLKS + RP_BLKS + ZR_BLKS) {
        // ---- Wkq fold ----
        float* sA = sbuf;             // Wk 64x64
        float* sB = sbuf + 64 * 64;   // Wq 64x20
        for (int i = tid; i < 64 * 64; i += 256) sA[i] = Wk[i];
        for (int i = tid; i < 64 * CR; i += 256) sB[i] = Wq[i];
        __syncthreads();
        for (int i = tid; i < CR * 64; i += 256) {
            int c = i >> 6, f = i & 63;
            float s = 0.f;
#pragma unroll
            for (int e = 0; e < 64; e++) s += sA[e * 64 + f] * sB[e * CR + c];
            g_WkqT[i] = s;  // [c][f]
        }
    } else {
        // ---- Wov fold (2 blocks) ----
        int half = blk - (TR_BLKS + RP_BLKS + ZR_BLKS + 1);  // 0 or 1
        float* sA = sbuf;             // Wv
        float* sB = sbuf + 64 * 64;   // Wo
        for (int i = tid; i < 64 * 64; i += 256) sA[i] = Wv[i];
        for (int i = tid; i < 64 * 64; i += 256) sB[i] = Wo[i];
        __syncthreads();
        for (int ii = half * 2048 + tid; ii < half * 2048 + 2048; ii += 256) {
            int f = ii >> 6, o = ii & 63;
            float s = 0.f;
#pragma unroll
            for (int e = 0; e < 64; e++) s += sB[o * 64 + e] * sA[e * 64 + f];
            g_WovT[ii] = s;  // [f][o]
        }
    }
}

// ---------------- dense q GEMM: g_qd[b][m][f] = sum_c r_feat[b][c][m] * Wkq[c][f] ----------------
#define QD_TILE 128
#define QD_PAD 132
__global__ __launch_bounds__(256) void qd_kernel(const float* __restrict__ r_feat) {
    __shared__ float sW[CR * 64];       // [c][f]
    __shared__ float sR[CR * QD_PAD];   // [c][m-local]

    int tid = threadIdx.x;
    int b = blockIdx.y;
    int m0 = blockIdx.x * QD_TILE;

    for (int i = tid; i < CR * 64; i += 256) sW[i] = g_WkqT[i];
    for (int i = tid; i < CR * QD_TILE; i += 256) {
        int c = i / QD_TILE;
        int m = i - c * QD_TILE;
        float v = 0.f;
        if (m0 + m < MR) v = r_feat[((size_t)b * CR + c) * MR + m0 + m];
        sR[c * QD_PAD + m] = v;
    }
    __syncthreads();

    int f0 = (tid & 7) * 8;
    int ml0 = (tid >> 3) * 4;

    ull acc2[4][4];   // p = f-pair, j = m
#pragma unroll
    for (int p = 0; p < 4; p++)
#pragma unroll
        for (int j = 0; j < 4; j++) acc2[p][j] = 0ull;

#pragma unroll
    for (int c = 0; c < CR; c++) {
        const float* wrow = sW + c * 64 + f0;
        ull w2[4];
#pragma unroll
        for (int p = 0; p < 4; p++) w2[p] = *(const ull*)(wrow + 2 * p);
        const float* vrow = sR + c * QD_PAD + ml0;
        ull v2[4];
#pragma unroll
        for (int j = 0; j < 4; j++) {
            float vj = vrow[j];
            asm("mov.b64 %0, {%1, %1};" : "=l"(v2[j]) : "f"(vj));
        }
#pragma unroll
        for (int p = 0; p < 4; p++)
#pragma unroll
            for (int j = 0; j < 4; j++)
                asm("fma.rn.f32x2 %0, %1, %2, %0;"
                    : "+l"(acc2[p][j]) : "l"(w2[p]), "l"(v2[j]));
    }

#pragma unroll
    for (int j = 0; j < 4; j++) {
        int m = m0 + ml0 + j;
        if (m < MR) {
            float a[8];
#pragma unroll
            for (int p = 0; p < 4; p++)
                asm("mov.b64 {%0, %1}, %2;" : "=f"(a[2 * p]), "=f"(a[2 * p + 1])
                    : "l"(acc2[p][j]));
            float* dst = g_qd + ((size_t)b * MR + m) * 64 + f0;
            *(float4*)dst = make_float4(a[0], a[1], a[2], a[3]);
            *(float4*)(dst + 4) = make_float4(a[4], a[5], a[6], a[7]);
        }
    }
}

// ---------------- attention: gather q + v (batched loads), softmax, RED into g_vbar ----------------
__global__ __launch_bounds__(256) void attn_kernel() {
    const unsigned FULL = 0xffffffffu;
    int gw = (blockIdx.x * 256 + threadIdx.x) >> 5;  // warp id, 4 bundles each
    int lane = threadIdx.x & 31;
    int sub = lane >> 3;
    int fl = lane & 7;

    int n = gw * 4 + sub;
    int b = n >> 16;

    // lanes 0..15: iv (16 values); lanes 16..19: ir (4 values)
    int ldv = 0;
    if (lane < 16) ldv = g_iv[(size_t)gw * 16 + lane];
    else if (lane < 20) ldv = g_ir[gw * 4 + (lane - 16)];

    // resolve ALL indices first, then issue all 10 gathers back-to-back (max MLP)
    int ir_n = __shfl_sync(FULL, ldv, 16 + sub);
    int ivm[4];
#pragma unroll
    for (int m = 0; m < 4; m++) ivm[m] = __shfl_sync(FULL, ldv, sub * 4 + m);

    const float4* qp = (const float4*)(g_qd + ((size_t)b * MR + ir_n) * 64 + fl * 8);
    float4 q0 = qp[0];
    float4 q1 = qp[1];

    const float* vbase = g_vT + (size_t)b * MV * 64;
    float4 v0[4], v1[4];
#pragma unroll
    for (int m = 0; m < 4; m++) {
        const float4* vp = (const float4*)(vbase + (size_t)ivm[m] * 64 + fl * 8);
        v0[m] = vp[0];
        v1[m] = vp[1];
    }

    float s[4];
#pragma unroll
    for (int m = 0; m < 4; m++) {
        float p = q0.x * v0[m].x + q0.y * v0[m].y + q0.z * v0[m].z + q0.w * v0[m].w
                + q1.x * v1[m].x + q1.y * v1[m].y + q1.z * v1[m].z + q1.w * v1[m].w;
        p += __shfl_xor_sync(FULL, p, 4);
        p += __shfl_xor_sync(FULL, p, 2);
        p += __shfl_xor_sync(FULL, p, 1);
        s[m] = p * 0.125f;  // 1/sqrt(E=64)
    }

    float mx = fmaxf(fmaxf(s[0], s[1]), fmaxf(s[2], s[3]));
    float e0 = __expf(s[0] - mx), e1 = __expf(s[1] - mx);
    float e2 = __expf(s[2] - mx), e3 = __expf(s[3] - mx);
    float inv = 1.0f / (e0 + e1 + e2 + e3);
    e0 *= inv; e1 *= inv; e2 *= inv; e3 *= inv;

    float4 o0, o1;
    o0.x = e0 * v0[0].x + e1 * v0[1].x + e2 * v0[2].x + e3 * v0[3].x;
    o0.y = e0 * v0[0].y + e1 * v0[1].y + e2 * v0[2].y + e3 * v0[3].y;
    o0.z = e0 * v0[0].z + e1 * v0[1].z + e2 * v0[2].z + e3 * v0[3].z;
    o0.w = e0 * v0[0].w + e1 * v0[1].w + e2 * v0[2].w + e3 * v0[3].w;
    o1.x = e0 * v1[0].x + e1 * v1[1].x + e2 * v1[2].x + e3 * v1[3].x;
    o1.y = e0 * v1[0].y + e1 * v1[1].y + e2 * v1[2].y + e3 * v1[3].y;
    o1.z = e0 * v1[0].z + e1 * v1[1].z + e2 * v1[2].z + e3 * v1[3].z;
    o1.w = e0 * v1[0].w + e1 * v1[1].w + e2 * v1[2].w + e3 * v1[3].w;

    float* dst = g_vbar + ((size_t)b * MR + ir_n) * 64 + fl * 8;
    asm volatile("red.global.add.v4.f32 [%0], {%1, %2, %3, %4};"
                 :: "l"(dst), "f"(o0.x), "f"(o0.y), "f"(o0.z), "f"(o0.w) : "memory");
    asm volatile("red.global.add.v4.f32 [%0], {%1, %2, %3, %4};"
                 :: "l"(dst + 4), "f"(o1.x), "f"(o1.y), "f"(o1.z), "f"(o1.w) : "memory");
}

// ---------------- dense output GEMM: out[b][o][m] = sum_f Wov[f][o] * vbar[m][f] ----------------
#define OPAD 260
#define OUT3_FLOATS (64 * 64 + 64 * OPAD)
#define OUT3_BYTES  (OUT3_FLOATS * 4)

__global__ __launch_bounds__(256) void out3_kernel(float* __restrict__ out) {
    extern __shared__ float dsm[];
    float* sW = dsm;                 // [f][o]
    float* sVT = dsm + 64 * 64;      // [f][cl]

    int tid = threadIdx.x;
    int b = blockIdx.y;
    int m0 = blockIdx.x * 256;

    {
        float4* d4 = (float4*)sW;
        const float4* s4 = (const float4*)g_WovT;
        for (int i = tid; i < 1024; i += 256) d4[i] = s4[i];
    }
    for (int i = tid; i < 256 * 16; i += 256) {
        int cl = i >> 4;
        int c4 = i & 15;
        int m = m0 + cl;
        float4 v = make_float4(0.f, 0.f, 0.f, 0.f);
        if (m < MR)
            v = *(const float4*)(g_vbar + ((size_t)b * MR + m) * 64 + c4 * 4);
        int f = c4 * 4;
        sVT[(f + 0) * OPAD + cl] = v.x;
        sVT[(f + 1) * OPAD + cl] = v.y;
        sVT[(f + 2) * OPAD + cl] = v.z;
        sVT[(f + 3) * OPAD + cl] = v.w;
    }
    __syncthreads();

    int o0 = (tid & 7) * 8;
    int ml0 = (tid >> 3) * 8;

    ull acc2[4][8];   // p = m-pair, j = o
#pragma unroll
    for (int p = 0; p < 4; p++)
#pragma unroll
        for (int j = 0; j < 8; j++) acc2[p][j] = 0ull;

#pragma unroll 4
    for (int f = 0; f < 64; f++) {
        const float* wrow = sW + f * 64 + o0;
        float4 w0 = *(const float4*)wrow;
        float4 w1 = *(const float4*)(wrow + 4);
        float w[8] = {w0.x, w0.y, w0.z, w0.w, w1.x, w1.y, w1.z, w1.w};
        ull w2[8];
#pragma unroll
        for (int j = 0; j < 8; j++)
            asm("mov.b64 %0, {%1, %1};" : "=l"(w2[j]) : "f"(w[j]));
        const float* vrow = sVT + f * OPAD + ml0;
        ull v2[4];
#pragma unroll
        for (int p = 0; p < 4; p++) v2[p] = *(const ull*)(vrow + 2 * p);
#pragma unroll
        for (int p = 0; p < 4; p++)
#pragma unroll
            for (int j = 0; j < 8; j++)
                asm("fma.rn.f32x2 %0, %1, %2, %0;"
                    : "+l"(acc2[p][j]) : "l"(v2[p]), "l"(w2[j]));
    }

    if (m0 + ml0 < MR) {
#pragma unroll
        for (int j = 0; j < 8; j++) {
            int o = o0 + j;
            float a[8];
#pragma unroll
            for (int p = 0; p < 4; p++)
                asm("mov.b64 {%0, %1}, %2;" : "=f"(a[2 * p]), "=f"(a[2 * p + 1])
                    : "l"(acc2[p][j]));
            float* dst = out + ((size_t)b * CO + o) * MR + m0 + ml0;
            *(float4*)dst = make_float4(a[0], a[1], a[2], a[3]);
            *(float4*)(dst + 4) = make_float4(a[4], a[5], a[6], a[7]);
        }
    }
}

// ---------------- launch ----------------
extern "C" void kernel_launch(void* const* d_in, const int* in_sizes, int n_in,
                              void* d_out, int out_size) {
    const float* v_feat = (const float*)d_in[0];
    const float* r_feat = (const float*)d_in[1];
    const float* Wq = (const float*)d_in[2];
    const float* Wk = (const float*)d_in[3];
    const float* Wv = (const float*)d_in[4];
    const float* Wo = (const float*)d_in[5];
    const void* v2p = d_in[6];
    const void* r2p = d_in[7];
    float* out = (float*)d_out;

    cudaFuncSetAttribute(out3_kernel, cudaFuncAttributeMaxDynamicSharedMemorySize,
                         OUT3_BYTES);

    // 1) phase1: vT transpose || repack || zero || weight folds (one launch)
    phase1_kernel<<<P1_GRID, 256>>>(v_feat, v2p, r2p, Wq, Wk, Wv, Wo);

    // 2) dense q GEMM straight from r_feat
    qd_kernel<<<dim3((MR + QD_TILE - 1) / QD_TILE, B_), 256>>>(r_feat);

    // 3) attention: batched gathers, softmax, RED into g_vbar
    attn_kernel<<<TOTN / 32, 256>>>();

    // 4) dense Wov GEMM + direct store into final layout
    out3_kernel<<<dim3((MR + 255) / 256, B_), 256, OUT3_BYTES>>>(out);
}

// round 11
// speedup vs baseline: 1.2472x; 1.1076x over previous
#include <cuda_runtime.h>
#include <cstddef>

// Problem constants (fixed by setup_inputs)
#define B_   2
#define CV   64
#define CR   20
#define E_   64
#define CO   64
#define MV   100000
#define MR   50000
#define NV   262144      // v2p count per batch
#define NN   65536       // bundles per batch (N / bundle, bundle = 4)
#define TOTN (B_ * NN)   // 131072
#define CELLS (B_ * MR)  // 100000

typedef unsigned long long ull;

// ---------------- scratch (device globals: allocation-free) ----------------
__device__ float g_vT[(size_t)B_ * MV * CV];    // v_feat transposed: (B, Mv, 64)
__device__ float g_qd[(size_t)CELLS * 64];      // dense q per cell: (B, Mr, 64)
__device__ float g_vbar[(size_t)CELLS * 64];    // per-cell summed vbar (RED target)
__device__ float g_WkqT[CR * 64];               // [c][f]
__device__ float g_WovT[64 * 64];               // [f][o]
__device__ int   g_iv[(size_t)B_ * NV];         // v indices (int32)
__device__ int   g_ir[(size_t)TOTN];            // r indices (int32)

__device__ __forceinline__ bool detect_int64(const int* __restrict__ p) {
    bool i64 = true;
#pragma unroll
    for (int i = 1; i < 32; i += 2) i64 &= (p[i] == 0);
    return i64;
}

// ---------------- phase1: vT transpose (vectorized) + repack + zero + weight folds ----
// transpose: 64 m x 64 c tiles, float4 on both global sides
#define TR_BX ((MV + 63) / 64)           // 1563
#define TR_BLKS (TR_BX * B_)             // 3126
#define RP_BLKS 256
#define ZR_BLKS 128
#define P1_GRID (TR_BLKS + RP_BLKS + ZR_BLKS + 3)

__global__ __launch_bounds__(256) void phase1_kernel(
    const float* __restrict__ v_feat,
    const void* __restrict__ v2p, const void* __restrict__ r2p,
    const float* __restrict__ Wq, const float* __restrict__ Wk,
    const float* __restrict__ Wv, const float* __restrict__ Wo) {
    __shared__ float sbuf[64 * 65 + 64 * 64];   // union: transpose tile / fold operands

    int blk = blockIdx.x;
    int tid = threadIdx.x;

    if (blk < TR_BLKS) {
        // ---- v transpose: (B, 64, Mv) -> (B, Mv, 64), float4 both sides ----
        float (*tile)[65] = (float (*)[65])sbuf;   // [m_local][c]
        int bx = blk % TR_BX;
        int b = blk / TR_BX;
        int m0 = bx * 64;
        const float* inb = v_feat + (size_t)b * CV * MV;
        float* outb = g_vT + (size_t)b * MV * CV;

        // load: 64 c-rows x 16 float4 along m
#pragma unroll
        for (int j = 0; j < 4; j++) {
            int idx = tid + j * 256;
            int c = idx >> 4;
            int mq = idx & 15;
            int m = m0 + mq * 4;
            if (m < MV) {   // MV % 4 == 0, so whole float4 is in-bounds
                float4 v = *(const float4*)(inb + (size_t)c * MV + m);
                tile[mq * 4 + 0][c] = v.x;
                tile[mq * 4 + 1][c] = v.y;
                tile[mq * 4 + 2][c] = v.z;
                tile[mq * 4 + 3][c] = v.w;
            }
        }
        __syncthreads();
        // store: 64 m-rows x 16 float4 along c
#pragma unroll
        for (int j = 0; j < 4; j++) {
            int idx = tid + j * 256;
            int ml = idx >> 4;
            int cq = idx & 15;
            int m = m0 + ml;
            if (m < MV) {
                float4 v = make_float4(tile[ml][cq * 4 + 0], tile[ml][cq * 4 + 1],
                                       tile[ml][cq * 4 + 2], tile[ml][cq * 4 + 3]);
                *(float4*)(outb + (size_t)m * CV + cq * 4) = v;
            }
        }
    } else if (blk < TR_BLKS + RP_BLKS) {
        // ---- index repack (int32 or int64 source) ----
        const int* pv = (const int*)v2p;
        const int* pr = (const int*)r2p;
        bool v64 = detect_int64(pv);
        bool r64 = detect_int64(pr);
        int t = (blk - TR_BLKS) * 256 + tid;
        int stride = RP_BLKS * 256;
        for (int i = t; i < B_ * NV; i += stride)
            g_iv[i] = v64 ? pv[(size_t)4 * i] : pv[(size_t)2 * i];
        for (int i = t; i < TOTN; i += stride)
            g_ir[i] = r64 ? pr[(size_t)4 * i] : pr[(size_t)2 * i];
    } else if (blk < TR_BLKS + RP_BLKS + ZR_BLKS) {
        // ---- zero RED accumulator ----
        float4* p = (float4*)g_vbar;
        int n4 = (CELLS * 64) / 4;
        int t = (blk - TR_BLKS - RP_BLKS) * 256 + tid;
        int stride = ZR_BLKS * 256;
        float4 z = make_float4(0.f, 0.f, 0.f, 0.f);
        for (int i = t; i < n4; i += stride) p[i] = z;
    } else if (blk == TR_BLKS + RP_BLKS + ZR_BLKS) {
        // ---- Wkq fold ----
        float* sA = sbuf;             // Wk 64x64
        float* sB = sbuf + 64 * 65;   // Wq 64x20
        for (int i = tid; i < 64 * 64; i += 256) sA[i] = Wk[i];
        for (int i = tid; i < 64 * CR; i += 256) sB[i] = Wq[i];
        __syncthreads();
        for (int i = tid; i < CR * 64; i += 256) {
            int c = i >> 6, f = i & 63;
            float s = 0.f;
#pragma unroll
            for (int e = 0; e < 64; e++) s += sA[e * 64 + f] * sB[e * CR + c];
            g_WkqT[i] = s;  // [c][f]
        }
    } else {
        // ---- Wov fold (2 blocks) ----
        int half = blk - (TR_BLKS + RP_BLKS + ZR_BLKS + 1);  // 0 or 1
        float* sA = sbuf;             // Wv
        float* sB = sbuf + 64 * 65;   // Wo
        for (int i = tid; i < 64 * 64; i += 256) sA[i] = Wv[i];
        for (int i = tid; i < 64 * 64; i += 256) sB[i] = Wo[i];
        __syncthreads();
        for (int ii = half * 2048 + tid; ii < half * 2048 + 2048; ii += 256) {
            int f = ii >> 6, o = ii & 63;
            float s = 0.f;
#pragma unroll
            for (int e = 0; e < 64; e++) s += sB[o * 64 + e] * sA[e * 64 + f];
            g_WovT[ii] = s;  // [f][o]
        }
    }
}

// ---------------- dense q GEMM: g_qd[b][m][f] = sum_c r_feat[b][c][m] * Wkq[c][f] ----------------
#define QD_TILE 128
#define QD_PAD 132
__global__ __launch_bounds__(256) void qd_kernel(const float* __restrict__ r_feat) {
    __shared__ float sW[CR * 64];       // [c][f]
    __shared__ float sR[CR * QD_PAD];   // [c][m-local]

    int tid = threadIdx.x;
    int b = blockIdx.y;
    int m0 = blockIdx.x * QD_TILE;

    for (int i = tid; i < CR * 64; i += 256) sW[i] = g_WkqT[i];
    for (int i = tid; i < CR * QD_TILE; i += 256) {
        int c = i / QD_TILE;
        int m = i - c * QD_TILE;
        float v = 0.f;
        if (m0 + m < MR) v = r_feat[((size_t)b * CR + c) * MR + m0 + m];
        sR[c * QD_PAD + m] = v;
    }
    __syncthreads();

    int f0 = (tid & 7) * 8;
    int ml0 = (tid >> 3) * 4;

    ull acc2[4][4];   // p = f-pair, j = m
#pragma unroll
    for (int p = 0; p < 4; p++)
#pragma unroll
        for (int j = 0; j < 4; j++) acc2[p][j] = 0ull;

#pragma unroll
    for (int c = 0; c < CR; c++) {
        const float* wrow = sW + c * 64 + f0;
        ull w2[4];
#pragma unroll
        for (int p = 0; p < 4; p++) w2[p] = *(const ull*)(wrow + 2 * p);
        const float* vrow = sR + c * QD_PAD + ml0;
        ull v2[4];
#pragma unroll
        for (int j = 0; j < 4; j++) {
            float vj = vrow[j];
            asm("mov.b64 %0, {%1, %1};" : "=l"(v2[j]) : "f"(vj));
        }
#pragma unroll
        for (int p = 0; p < 4; p++)
#pragma unroll
            for (int j = 0; j < 4; j++)
                asm("fma.rn.f32x2 %0, %1, %2, %0;"
                    : "+l"(acc2[p][j]) : "l"(w2[p]), "l"(v2[j]));
    }

#pragma unroll
    for (int j = 0; j < 4; j++) {
        int m = m0 + ml0 + j;
        if (m < MR) {
            float a[8];
#pragma unroll
            for (int p = 0; p < 4; p++)
                asm("mov.b64 {%0, %1}, %2;" : "=f"(a[2 * p]), "=f"(a[2 * p + 1])
                    : "l"(acc2[p][j]));
            float* dst = g_qd + ((size_t)b * MR + m) * 64 + f0;
            *(float4*)dst = make_float4(a[0], a[1], a[2], a[3]);
            *(float4*)(dst + 4) = make_float4(a[4], a[5], a[6], a[7]);
        }
    }
}

// ---------------- attention: gather q + v (batched loads), softmax, RED into g_vbar ----------------
__global__ __launch_bounds__(256) void attn_kernel() {
    const unsigned FULL = 0xffffffffu;
    int gw = (blockIdx.x * 256 + threadIdx.x) >> 5;  // warp id, 4 bundles each
    int lane = threadIdx.x & 31;
    int sub = lane >> 3;
    int fl = lane & 7;

    int n = gw * 4 + sub;
    int b = n >> 16;

    // lanes 0..15: iv (16 values); lanes 16..19: ir (4 values)
    int ldv = 0;
    if (lane < 16) ldv = g_iv[(size_t)gw * 16 + lane];
    else if (lane < 20) ldv = g_ir[gw * 4 + (lane - 16)];

    int ir_n = __shfl_sync(FULL, ldv, 16 + sub);
    int ivm[4];
#pragma unroll
    for (int m = 0; m < 4; m++) ivm[m] = __shfl_sync(FULL, ldv, sub * 4 + m);

    const float4* qp = (const float4*)(g_qd + ((size_t)b * MR + ir_n) * 64 + fl * 8);
    float4 q0 = qp[0];
    float4 q1 = qp[1];

    const float* vbase = g_vT + (size_t)b * MV * 64;
    float4 v0[4], v1[4];
#pragma unroll
    for (int m = 0; m < 4; m++) {
        const float4* vp = (const float4*)(vbase + (size_t)ivm[m] * 64 + fl * 8);
        v0[m] = vp[0];
        v1[m] = vp[1];
    }

    float s[4];
#pragma unroll
    for (int m = 0; m < 4; m++) {
        float p = q0.x * v0[m].x + q0.y * v0[m].y + q0.z * v0[m].z + q0.w * v0[m].w
                + q1.x * v1[m].x + q1.y * v1[m].y + q1.z * v1[m].z + q1.w * v1[m].w;
        p += __shfl_xor_sync(FULL, p, 4);
        p += __shfl_xor_sync(FULL, p, 2);
        p += __shfl_xor_sync(FULL, p, 1);
        s[m] = p * 0.125f;  // 1/sqrt(E=64)
    }

    float mx = fmaxf(fmaxf(s[0], s[1]), fmaxf(s[2], s[3]));
    float e0 = __expf(s[0] - mx), e1 = __expf(s[1] - mx);
    float e2 = __expf(s[2] - mx), e3 = __expf(s[3] - mx);
    float inv = 1.0f / (e0 + e1 + e2 + e3);
    e0 *= inv; e1 *= inv; e2 *= inv; e3 *= inv;

    float4 o0, o1;
    o0.x = e0 * v0[0].x + e1 * v0[1].x + e2 * v0[2].x + e3 * v0[3].x;
    o0.y = e0 * v0[0].y + e1 * v0[1].y + e2 * v0[2].y + e3 * v0[3].y;
    o0.z = e0 * v0[0].z + e1 * v0[1].z + e2 * v0[2].z + e3 * v0[3].z;
    o0.w = e0 * v0[0].w + e1 * v0[1].w + e2 * v0[2].w + e3 * v0[3].w;
    o1.x = e0 * v1[0].x + e1 * v1[1].x + e2 * v1[2].x + e3 * v1[3].x;
    o1.y = e0 * v1[0].y + e1 * v1[1].y + e2 * v1[2].y + e3 * v1[3].y;
    o1.z = e0 * v1[0].z + e1 * v1[1].z + e2 * v1[2].z + e3 * v1[3].z;
    o1.w = e0 * v1[0].w + e1 * v1[1].w + e2 * v1[2].w + e3 * v1[3].w;

    float* dst = g_vbar + ((size_t)b * MR + ir_n) * 64 + fl * 8;
    asm volatile("red.global.add.v4.f32 [%0], {%1, %2, %3, %4};"
                 :: "l"(dst), "f"(o0.x), "f"(o0.y), "f"(o0.z), "f"(o0.w) : "memory");
    asm volatile("red.global.add.v4.f32 [%0], {%1, %2, %3, %4};"
                 :: "l"(dst + 4), "f"(o1.x), "f"(o1.y), "f"(o1.z), "f"(o1.w) : "memory");
}

// ---------------- dense output GEMM: out[b][o][m] = sum_f Wov[f][o] * vbar[m][f] ----------------
// 128 cells/block, thread tile 4m x 8o: ~60 regs + 49KB smem -> 4 blocks/SM
#define OTILE 128
#define OPAD 132
#define OUT3_FLOATS (64 * 64 + 64 * OPAD)
#define OUT3_BYTES  (OUT3_FLOATS * 4)

__global__ __launch_bounds__(256) void out3_kernel(float* __restrict__ out) {
    extern __shared__ float dsm[];
    float* sW = dsm;                 // [f][o]
    float* sVT = dsm + 64 * 64;      // [f][cl]

    int tid = threadIdx.x;
    int b = blockIdx.y;
    int m0 = blockIdx.x * OTILE;

    {
        float4* d4 = (float4*)sW;
        const float4* s4 = (const float4*)g_WovT;
        for (int i = tid; i < 1024; i += 256) d4[i] = s4[i];
    }
    for (int i = tid; i < OTILE * 16; i += 256) {
        int cl = i >> 4;
        int c4 = i & 15;
        int m = m0 + cl;
        float4 v = make_float4(0.f, 0.f, 0.f, 0.f);
        if (m < MR)
            v = *(const float4*)(g_vbar + ((size_t)b * MR + m) * 64 + c4 * 4);
        int f = c4 * 4;
        sVT[(f + 0) * OPAD + cl] = v.x;
        sVT[(f + 1) * OPAD + cl] = v.y;
        sVT[(f + 2) * OPAD + cl] = v.z;
        sVT[(f + 3) * OPAD + cl] = v.w;
    }
    __syncthreads();

    int o0 = (tid & 7) * 8;
    int ml0 = (tid >> 3) * 4;

    ull acc2[2][8];   // p = m-pair, j = o
#pragma unroll
    for (int p = 0; p < 2; p++)
#pragma unroll
        for (int j = 0; j < 8; j++) acc2[p][j] = 0ull;

#pragma unroll 4
    for (int f = 0; f < 64; f++) {
        const float* wrow = sW + f * 64 + o0;
        float4 w0 = *(const float4*)wrow;
        float4 w1 = *(const float4*)(wrow + 4);
        float w[8] = {w0.x, w0.y, w0.z, w0.w, w1.x, w1.y, w1.z, w1.w};
        ull w2[8];
#pragma unroll
        for (int j = 0; j < 8; j++)
            asm("mov.b64 %0, {%1, %1};" : "=l"(w2[j]) : "f"(w[j]));
        const float* vrow = sVT + f * OPAD + ml0;
        ull v2[2];
#pragma unroll
        for (int p = 0; p < 2; p++) v2[p] = *(const ull*)(vrow + 2 * p);
#pragma unroll
        for (int p = 0; p < 2; p++)
#pragma unroll
            for (int j = 0; j < 8; j++)
                asm("fma.rn.f32x2 %0, %1, %2, %0;"
                    : "+l"(acc2[p][j]) : "l"(v2[p]), "l"(w2[j]));
    }

    if (m0 + ml0 < MR) {
#pragma unroll
        for (int j = 0; j < 8; j++) {
            int o = o0 + j;
            float a[4];
#pragma unroll
            for (int p = 0; p < 2; p++)
                asm("mov.b64 {%0, %1}, %2;" : "=f"(a[2 * p]), "=f"(a[2 * p + 1])
                    : "l"(acc2[p][j]));
            float* dst = out + ((size_t)b * CO + o) * MR + m0 + ml0;
            *(float4*)dst = make_float4(a[0], a[1], a[2], a[3]);
        }
    }
}

// ---------------- launch ----------------
extern "C" void kernel_launch(void* const* d_in, const int* in_sizes, int n_in,
                              void* d_out, int out_size) {
    const float* v_feat = (const float*)d_in[0];
    const float* r_feat = (const float*)d_in[1];
    const float* Wq = (const float*)d_in[2];
    const float* Wk = (const float*)d_in[3];
    const float* Wv = (const float*)d_in[4];
    const float* Wo = (const float*)d_in[5];
    const void* v2p = d_in[6];
    const void* r2p = d_in[7];
    float* out = (float*)d_out;

    cudaFuncSetAttribute(out3_kernel, cudaFuncAttributeMaxDynamicSharedMemorySize,
                         OUT3_BYTES);

    // 1) phase1: vT transpose (float4 both sides) || repack || zero || folds
    phase1_kernel<<<P1_GRID, 256>>>(v_feat, v2p, r2p, Wq, Wk, Wv, Wo);

    // 2) dense q GEMM straight from r_feat
    qd_kernel<<<dim3((MR + QD_TILE - 1) / QD_TILE, B_), 256>>>(r_feat);

    // 3) attention: batched gathers, softmax, RED into g_vbar
    attn_kernel<<<TOTN / 32, 256>>>();

    // 4) dense Wov GEMM + direct store (128 cells, 4m x 8o tile)
    out3_kernel<<<dim3((MR + OTILE - 1) / OTILE, B_), 256, OUT3_BYTES>>>(out);
}

// round 12
// speedup vs baseline: 1.4195x; 1.1381x over previous
#include <cuda_runtime.h>
#include <cstddef>

// Problem constants (fixed by setup_inputs)
#define B_   2
#define CV   64
#define CR   20
#define E_   64
#define CO   64
#define MV   100000
#define MR   50000
#define NV   262144      // v2p count per batch
#define NN   65536       // bundles per batch (N / bundle, bundle = 4)
#define TOTN (B_ * NN)   // 131072
#define CELLS (B_ * MR)  // 100000

typedef unsigned long long ull;

// ---------------- scratch (device globals: allocation-free) ----------------
__device__ float g_vT[(size_t)B_ * MV * CV];    // v_feat transposed: (B, Mv, 64)
__device__ float g_qd[(size_t)CELLS * 64];      // dense q per cell: (B, Mr, 64)
__device__ float g_vbar[(size_t)CELLS * 64];    // per-cell summed vbar (RED target)
__device__ float g_WkqT[CR * 64];               // [c][f]
__device__ float g_WovT[64 * 64];               // [f][o]
__device__ int   g_iv[(size_t)B_ * NV];         // v indices (int32)
__device__ int   g_ir[(size_t)TOTN];            // r indices (int32)

__device__ __forceinline__ bool detect_int64(const int* __restrict__ p) {
    bool i64 = true;
#pragma unroll
    for (int i = 1; i < 32; i += 2) i64 &= (p[i] == 0);
    return i64;
}

// ---------------- phase1: vT transpose (vectorized) + repack + zero + weight folds ----
#define TR_BX ((MV + 63) / 64)           // 1563
#define TR_BLKS (TR_BX * B_)             // 3126
#define RP_BLKS 256
#define ZR_BLKS 128
#define P1_GRID (TR_BLKS + RP_BLKS + ZR_BLKS + 3)

__global__ __launch_bounds__(256) void phase1_kernel(
    const float* __restrict__ v_feat,
    const void* __restrict__ v2p, const void* __restrict__ r2p,
    const float* __restrict__ Wq, const float* __restrict__ Wk,
    const float* __restrict__ Wv, const float* __restrict__ Wo) {
    __shared__ float sbuf[64 * 65 + 64 * 64];   // union: transpose tile / fold operands

    int blk = blockIdx.x;
    int tid = threadIdx.x;

    if (blk < TR_BLKS) {
        // ---- v transpose: (B, 64, Mv) -> (B, Mv, 64), float4 both sides ----
        float (*tile)[65] = (float (*)[65])sbuf;   // [m_local][c]
        int bx = blk % TR_BX;
        int b = blk / TR_BX;
        int m0 = bx * 64;
        const float* inb = v_feat + (size_t)b * CV * MV;
        float* outb = g_vT + (size_t)b * MV * CV;

#pragma unroll
        for (int j = 0; j < 4; j++) {
            int idx = tid + j * 256;
            int c = idx >> 4;
            int mq = idx & 15;
            int m = m0 + mq * 4;
            if (m < MV) {   // MV % 4 == 0
                float4 v = *(const float4*)(inb + (size_t)c * MV + m);
                tile[mq * 4 + 0][c] = v.x;
                tile[mq * 4 + 1][c] = v.y;
                tile[mq * 4 + 2][c] = v.z;
                tile[mq * 4 + 3][c] = v.w;
            }
        }
        __syncthreads();
#pragma unroll
        for (int j = 0; j < 4; j++) {
            int idx = tid + j * 256;
            int ml = idx >> 4;
            int cq = idx & 15;
            int m = m0 + ml;
            if (m < MV) {
                float4 v = make_float4(tile[ml][cq * 4 + 0], tile[ml][cq * 4 + 1],
                                       tile[ml][cq * 4 + 2], tile[ml][cq * 4 + 3]);
                *(float4*)(outb + (size_t)m * CV + cq * 4) = v;
            }
        }
    } else if (blk < TR_BLKS + RP_BLKS) {
        const int* pv = (const int*)v2p;
        const int* pr = (const int*)r2p;
        bool v64 = detect_int64(pv);
        bool r64 = detect_int64(pr);
        int t = (blk - TR_BLKS) * 256 + tid;
        int stride = RP_BLKS * 256;
        for (int i = t; i < B_ * NV; i += stride)
            g_iv[i] = v64 ? pv[(size_t)4 * i] : pv[(size_t)2 * i];
        for (int i = t; i < TOTN; i += stride)
            g_ir[i] = r64 ? pr[(size_t)4 * i] : pr[(size_t)2 * i];
    } else if (blk < TR_BLKS + RP_BLKS + ZR_BLKS) {
        float4* p = (float4*)g_vbar;
        int n4 = (CELLS * 64) / 4;
        int t = (blk - TR_BLKS - RP_BLKS) * 256 + tid;
        int stride = ZR_BLKS * 256;
        float4 z = make_float4(0.f, 0.f, 0.f, 0.f);
        for (int i = t; i < n4; i += stride) p[i] = z;
    } else if (blk == TR_BLKS + RP_BLKS + ZR_BLKS) {
        float* sA = sbuf;             // Wk 64x64
        float* sB = sbuf + 64 * 65;   // Wq 64x20
        for (int i = tid; i < 64 * 64; i += 256) sA[i] = Wk[i];
        for (int i = tid; i < 64 * CR; i += 256) sB[i] = Wq[i];
        __syncthreads();
        for (int i = tid; i < CR * 64; i += 256) {
            int c = i >> 6, f = i & 63;
            float s = 0.f;
#pragma unroll
            for (int e = 0; e < 64; e++) s += sA[e * 64 + f] * sB[e * CR + c];
            g_WkqT[i] = s;  // [c][f]
        }
    } else {
        int half = blk - (TR_BLKS + RP_BLKS + ZR_BLKS + 1);  // 0 or 1
        float* sA = sbuf;             // Wv
        float* sB = sbuf + 64 * 65;   // Wo
        for (int i = tid; i < 64 * 64; i += 256) sA[i] = Wv[i];
        for (int i = tid; i < 64 * 64; i += 256) sB[i] = Wo[i];
        __syncthreads();
        for (int ii = half * 2048 + tid; ii < half * 2048 + 2048; ii += 256) {
            int f = ii >> 6, o = ii & 63;
            float s = 0.f;
#pragma unroll
            for (int e = 0; e < 64; e++) s += sB[o * 64 + e] * sA[e * 64 + f];
            g_WovT[ii] = s;  // [f][o]
        }
    }
}

// ---------------- dense q GEMM: g_qd[b][m][f] = sum_c r_feat[b][c][m] * Wkq[c][f] ----------------
#define QD_TILE 128
#define QD_PAD 132
__global__ __launch_bounds__(256) void qd_kernel(const float* __restrict__ r_feat) {
    __shared__ float sW[CR * 64];       // [c][f]
    __shared__ float sR[CR * QD_PAD];   // [c][m-local]

    int tid = threadIdx.x;
    int b = blockIdx.y;
    int m0 = blockIdx.x * QD_TILE;

    for (int i = tid; i < CR * 64; i += 256) sW[i] = g_WkqT[i];
    for (int i = tid; i < CR * QD_TILE; i += 256) {
        int c = i / QD_TILE;
        int m = i - c * QD_TILE;
        float v = 0.f;
        if (m0 + m < MR) v = r_feat[((size_t)b * CR + c) * MR + m0 + m];
        sR[c * QD_PAD + m] = v;
    }
    __syncthreads();

    int f0 = (tid & 7) * 8;
    int ml0 = (tid >> 3) * 4;

    ull acc2[4][4];   // p = f-pair, j = m
#pragma unroll
    for (int p = 0; p < 4; p++)
#pragma unroll
        for (int j = 0; j < 4; j++) acc2[p][j] = 0ull;

#pragma unroll
    for (int c = 0; c < CR; c++) {
        const float* wrow = sW + c * 64 + f0;
        ull w2[4];
#pragma unroll
        for (int p = 0; p < 4; p++) w2[p] = *(const ull*)(wrow + 2 * p);
        const float* vrow = sR + c * QD_PAD + ml0;
        ull v2[4];
#pragma unroll
        for (int j = 0; j < 4; j++) {
            float vj = vrow[j];
            asm("mov.b64 %0, {%1, %1};" : "=l"(v2[j]) : "f"(vj));
        }
#pragma unroll
        for (int p = 0; p < 4; p++)
#pragma unroll
            for (int j = 0; j < 4; j++)
                asm("fma.rn.f32x2 %0, %1, %2, %0;"
                    : "+l"(acc2[p][j]) : "l"(w2[p]), "l"(v2[j]));
    }

#pragma unroll
    for (int j = 0; j < 4; j++) {
        int m = m0 + ml0 + j;
        if (m < MR) {
            float a[8];
#pragma unroll
            for (int p = 0; p < 4; p++)
                asm("mov.b64 {%0, %1}, %2;" : "=f"(a[2 * p]), "=f"(a[2 * p + 1])
                    : "l"(acc2[p][j]));
            float* dst = g_qd + ((size_t)b * MR + m) * 64 + f0;
            *(float4*)dst = make_float4(a[0], a[1], a[2], a[3]);
            *(float4*)(dst + 4) = make_float4(a[4], a[5], a[6], a[7]);
        }
    }
}

// ---------------- attention: gather q + v (batched loads), softmax, RED into g_vbar ----------------
__global__ __launch_bounds__(256) void attn_kernel() {
    const unsigned FULL = 0xffffffffu;
    int gw = (blockIdx.x * 256 + threadIdx.x) >> 5;  // warp id, 4 bundles each
    int lane = threadIdx.x & 31;
    int sub = lane >> 3;
    int fl = lane & 7;

    int n = gw * 4 + sub;
    int b = n >> 16;

    int ldv = 0;
    if (lane < 16) ldv = g_iv[(size_t)gw * 16 + lane];
    else if (lane < 20) ldv = g_ir[gw * 4 + (lane - 16)];

    int ir_n = __shfl_sync(FULL, ldv, 16 + sub);
    int ivm[4];
#pragma unroll
    for (int m = 0; m < 4; m++) ivm[m] = __shfl_sync(FULL, ldv, sub * 4 + m);

    const float4* qp = (const float4*)(g_qd + ((size_t)b * MR + ir_n) * 64 + fl * 8);
    float4 q0 = qp[0];
    float4 q1 = qp[1];

    const float* vbase = g_vT + (size_t)b * MV * 64;
    float4 v0[4], v1[4];
#pragma unroll
    for (int m = 0; m < 4; m++) {
        const float4* vp = (const float4*)(vbase + (size_t)ivm[m] * 64 + fl * 8);
        v0[m] = vp[0];
        v1[m] = vp[1];
    }

    float s[4];
#pragma unroll
    for (int m = 0; m < 4; m++) {
        float p = q0.x * v0[m].x + q0.y * v0[m].y + q0.z * v0[m].z + q0.w * v0[m].w
                + q1.x * v1[m].x + q1.y * v1[m].y + q1.z * v1[m].z + q1.w * v1[m].w;
        p += __shfl_xor_sync(FULL, p, 4);
        p += __shfl_xor_sync(FULL, p, 2);
        p += __shfl_xor_sync(FULL, p, 1);
        s[m] = p * 0.125f;  // 1/sqrt(E=64)
    }

    float mx = fmaxf(fmaxf(s[0], s[1]), fmaxf(s[2], s[3]));
    float e0 = __expf(s[0] - mx), e1 = __expf(s[1] - mx);
    float e2 = __expf(s[2] - mx), e3 = __expf(s[3] - mx);
    float inv = 1.0f / (e0 + e1 + e2 + e3);
    e0 *= inv; e1 *= inv; e2 *= inv; e3 *= inv;

    float4 o0, o1;
    o0.x = e0 * v0[0].x + e1 * v0[1].x + e2 * v0[2].x + e3 * v0[3].x;
    o0.y = e0 * v0[0].y + e1 * v0[1].y + e2 * v0[2].y + e3 * v0[3].y;
    o0.z = e0 * v0[0].z + e1 * v0[1].z + e2 * v0[2].z + e3 * v0[3].z;
    o0.w = e0 * v0[0].w + e1 * v0[1].w + e2 * v0[2].w + e3 * v0[3].w;
    o1.x = e0 * v1[0].x + e1 * v1[1].x + e2 * v1[2].x + e3 * v1[3].x;
    o1.y = e0 * v1[0].y + e1 * v1[1].y + e2 * v1[2].y + e3 * v1[3].y;
    o1.z = e0 * v1[0].z + e1 * v1[1].z + e2 * v1[2].z + e3 * v1[3].z;
    o1.w = e0 * v1[0].w + e1 * v1[1].w + e2 * v1[2].w + e3 * v1[3].w;

    float* dst = g_vbar + ((size_t)b * MR + ir_n) * 64 + fl * 8;
    asm volatile("red.global.add.v4.f32 [%0], {%1, %2, %3, %4};"
                 :: "l"(dst), "f"(o0.x), "f"(o0.y), "f"(o0.z), "f"(o0.w) : "memory");
    asm volatile("red.global.add.v4.f32 [%0], {%1, %2, %3, %4};"
                 :: "l"(dst + 4), "f"(o1.x), "f"(o1.y), "f"(o1.z), "f"(o1.w) : "memory");
}

// ---------------- dense output GEMM: out[b][o][m] = sum_f Wov[f][o] * vbar[m][f] ----------------
// warp-broadcast layout: warp owns o-group (o0 = warp*8), lanes spread over m.
// Per warp per f: W row is a broadcast LDS (N=1), v is 16B/lane -> 0.53 B/FMA.
#define OTILE 128
#define OPAD 132
#define OUT3_FLOATS (64 * 64 + 64 * OPAD)
#define OUT3_BYTES  (OUT3_FLOATS * 4)

__global__ __launch_bounds__(256) void out3_kernel(float* __restrict__ out) {
    extern __shared__ float dsm[];
    float* sW = dsm;                 // [f][o]
    float* sVT = dsm + 64 * 64;      // [f][cl]

    int tid = threadIdx.x;
    int b = blockIdx.y;
    int m0 = blockIdx.x * OTILE;

    {
        float4* d4 = (float4*)sW;
        const float4* s4 = (const float4*)g_WovT;
        for (int i = tid; i < 1024; i += 256) d4[i] = s4[i];
    }
    for (int i = tid; i < OTILE * 16; i += 256) {
        int cl = i >> 4;
        int c4 = i & 15;
        int m = m0 + cl;
        float4 v = make_float4(0.f, 0.f, 0.f, 0.f);
        if (m < MR)
            v = *(const float4*)(g_vbar + ((size_t)b * MR + m) * 64 + c4 * 4);
        int f = c4 * 4;
        sVT[(f + 0) * OPAD + cl] = v.x;
        sVT[(f + 1) * OPAD + cl] = v.y;
        sVT[(f + 2) * OPAD + cl] = v.z;
        sVT[(f + 3) * OPAD + cl] = v.w;
    }
    __syncthreads();

    int warp = tid >> 5;
    int lane = tid & 31;
    int o0 = warp * 8;           // whole warp shares this o-group -> broadcast W reads
    int ml0 = lane * 4;          // lanes tile m

    ull acc2[2][8];   // p = m-pair (m, m+1), j = o
#pragma unroll
    for (int p = 0; p < 2; p++)
#pragma unroll
        for (int j = 0; j < 8; j++) acc2[p][j] = 0ull;

#pragma unroll 4
    for (int f = 0; f < 64; f++) {
        const float* wrow = sW + f * 64 + o0;   // same address across warp: broadcast
        float4 w0 = *(const float4*)wrow;
        float4 w1 = *(const float4*)(wrow + 4);
        float w[8] = {w0.x, w0.y, w0.z, w0.w, w1.x, w1.y, w1.z, w1.w};
        ull w2[8];
#pragma unroll
        for (int j = 0; j < 8; j++)
            asm("mov.b64 %0, {%1, %1};" : "=l"(w2[j]) : "f"(w[j]));
        const float* vrow = sVT + f * OPAD + ml0;
        ull v2[2];
#pragma unroll
        for (int p = 0; p < 2; p++) v2[p] = *(const ull*)(vrow + 2 * p);
#pragma unroll
        for (int p = 0; p < 2; p++)
#pragma unroll
            for (int j = 0; j < 8; j++)
                asm("fma.rn.f32x2 %0, %1, %2, %0;"
                    : "+l"(acc2[p][j]) : "l"(v2[p]), "l"(w2[j]));
    }

    if (m0 + ml0 + 3 < MR) {      // MR % 4 == 0, ml0 % 4 == 0 -> all-or-nothing
#pragma unroll
        for (int j = 0; j < 8; j++) {
            int o = o0 + j;
            float a[4];
#pragma unroll
            for (int p = 0; p < 2; p++)
                asm("mov.b64 {%0, %1}, %2;" : "=f"(a[2 * p]), "=f"(a[2 * p + 1])
                    : "l"(acc2[p][j]));
            float* dst = out + ((size_t)b * CO + o) * MR + m0 + ml0;
            *(float4*)dst = make_float4(a[0], a[1], a[2], a[3]);
        }
    }
}

// ---------------- launch ----------------
extern "C" void kernel_launch(void* const* d_in, const int* in_sizes, int n_in,
                              void* d_out, int out_size) {
    const float* v_feat = (const float*)d_in[0];
    const float* r_feat = (const float*)d_in[1];
    const float* Wq = (const float*)d_in[2];
    const float* Wk = (const float*)d_in[3];
    const float* Wv = (const float*)d_in[4];
    const float* Wo = (const float*)d_in[5];
    const void* v2p = d_in[6];
    const void* r2p = d_in[7];
    float* out = (float*)d_out;

    cudaFuncSetAttribute(out3_kernel, cudaFuncAttributeMaxDynamicSharedMemorySize,
                         OUT3_BYTES);

    // 1) phase1: vT transpose (float4 both sides) || repack || zero || folds
    phase1_kernel<<<P1_GRID, 256>>>(v_feat, v2p, r2p, Wq, Wk, Wv, Wo);

    // 2) dense q GEMM straight from r_feat
    qd_kernel<<<dim3((MR + QD_TILE - 1) / QD_TILE, B_), 256>>>(r_feat);

    // 3) attention: batched gathers, softmax, RED into g_vbar
    attn_kernel<<<TOTN / 32, 256>>>();

    // 4) dense Wov GEMM, warp-broadcast W + direct store
    out3_kernel<<<dim3((MR + OTILE - 1) / OTILE, B_), 256, OUT3_BYTES>>>(out);
}